// round 15
// baseline (speedup 1.0000x reference)
#include <cuda_runtime.h>

// Problem constants (B=64, S=512, H=768, W=MAX_WORD_LEN=256, VOCAB=50000, WE=300)
constexpr int B   = 64;
constexpr int S   = 512;
constexpr int H   = 768;
constexpr int W   = 256;
constexpr int WE  = 300;

constexpr int H4   = H  / 4;       // 192 float4 per transformer row
constexpr int WE4  = WE / 4;       // 75  float4 per w2v row
constexpr int OUT4 = H4 + WE4;     // 267 float4 per output row

constexpr int RW   = 3;            // warps per output row
constexpr int CH   = 2;            // H-part chunks per warp (192/32/3)

// ---------------------------------------------------------------------------
// Warp-cooperative lower_bound over a sorted 512-int row.
// tv1 = trow[16*lane] must be preloaded (shared by both calls).
// ---------------------------------------------------------------------------
__device__ __forceinline__ int warp_lower_bound(const int* __restrict__ trow,
                                                int tv1, int target, int lane)
{
    const unsigned m1 = __ballot_sync(0xffffffffu, tv1 < target);
    const int nlt = __popc(m1);          // sampled points with value < target
    if (nlt == 0) return 0;              // trow[0] >= target
    const int base = 16 * (nlt - 1) + 1; // answer in [base, base+15] (or S)
    const int idx  = base + lane;
    const int v    = (lane < 16 && idx < S) ? trow[idx] : 0x7fffffff;
    const unsigned m2 = __ballot_sync(0xffffffffu, v < target);
    return base + __popc(m2);
}

// ---------------------------------------------------------------------------
// Single fused kernel, THREE warps per output row (b, w); warp h owns
// H-chunks 2h, 2h+1 plus one 32-chunk slice of the w2v gather.
//
// R15 change vs R14: 3 warps/row (was 2) cuts loop-live registers to
// acc[2]+v[2] -> fits the 32-reg budget of __launch_bounds__(256, 8)
// = 8 CTAs/SM = 100% theoretical occupancy. Finer granularity also smooths
// segment-length imbalance across SMs.
// ---------------------------------------------------------------------------
__global__ void __launch_bounds__(256, 8)
embeddings_fused_kernel(const float4* __restrict__ hidden,     // [B, S, H4]
                        const float4* __restrict__ w2v,        // [VOCAB, WE4]
                        const int*    __restrict__ token_ids,  // [B, S]
                        const int*    __restrict__ word_ids,   // [B, W]
                        float4*       __restrict__ out)        // [B, W, OUT4]
{
    const int gwarp = (blockIdx.x << 3) | (threadIdx.x >> 5); // 0 .. 3*B*W-1
    const int lane  = threadIdx.x & 31;
    const int row   = gwarp / RW;            // output row (b*W + w)
    const int h     = gwarp - row * RW;      // 0, 1, 2
    const int b     = row >> 8;              // / W
    const int w     = row & (W - 1);

    float4* __restrict__ orow = out + (size_t)row * OUT4;

    // --- w2v gather: load -> store immediately (transient registers) -------
    {
        const int wid = word_ids[row];       // uniform broadcast load
        const float4* __restrict__ grow = w2v + (size_t)wid * WE4;
        const int gj = lane + 32 * h;        // warp h covers [32h, 32h+32)
        if (gj < WE4) __stcs(orow + H4 + gj, __ldg(grow + gj));
    }

    // --- warp-cooperative segment bounds -----------------------------------
    const int* __restrict__ trow = token_ids + b * S;
    const int tv1   = trow[lane << 4];       // sample trow[16*lane]
    const int start = warp_lower_bound(trow, tv1, w, lane);
    const int end   = warp_lower_bound(trow, tv1, w + 1, lane);
    const int count = end - start;
    const float inv = (count > 0) ? (1.0f / (float)count) : 0.0f;

    // --- token-major segment mean: 2 independent coalesced loads per token -
    const int col0 = lane + 32 * (CH * h);   // this warp's first column chunk
    const float4* p = hidden + ((size_t)b * S + start) * H4 + col0;

    float4 acc[CH];
    #pragma unroll
    for (int c = 0; c < CH; ++c) acc[c] = make_float4(0.f, 0.f, 0.f, 0.f);

    for (int t = 0; t < count; ++t, p += H4) {
        float4 v[CH];
        #pragma unroll
        for (int c = 0; c < CH; ++c) v[c] = __ldcs(p + 32 * c);
        #pragma unroll
        for (int c = 0; c < CH; ++c) {
            acc[c].x += v[c].x; acc[c].y += v[c].y;
            acc[c].z += v[c].z; acc[c].w += v[c].w;
        }
    }

    // --- write mean part (coalesced 512B per chunk) ------------------------
    #pragma unroll
    for (int c = 0; c < CH; ++c) {
        float4 r;
        r.x = acc[c].x * inv; r.y = acc[c].y * inv;
        r.z = acc[c].z * inv; r.w = acc[c].w * inv;
        __stcs(orow + col0 + 32 * c, r);
    }
}

extern "C" void kernel_launch(void* const* d_in, const int* in_sizes, int n_in,
                              void* d_out, int out_size)
{
    const float4* hidden    = (const float4*)d_in[0];   // [B,S,H] f32
    const float4* w2v       = (const float4*)d_in[1];   // [VOCAB,WE] f32
    const int*    token_ids = (const int*)d_in[2];      // [B,S]
    const int*    word_ids  = (const int*)d_in[3];      // [B,W]
    float4*       out       = (float4*)d_out;           // [B,W,H+WE] f32

    // 3 warps per row, 8 warps per CTA -> B*W*3/8 = 6144 CTAs
    embeddings_fused_kernel<<<(B * W * RW) / 8, 256>>>(hidden, w2v, token_ids,
                                                       word_ids, out);
}